// round 4
// baseline (speedup 1.0000x reference)
#include <cuda_runtime.h>
#include <math.h>

#define Bq 256
#define Tq 512
#define Iq 12
#define Hq 1024
#define Zq 128
#define G3 3072
#define NBLK 128
#define NTHR 256
#define OFF_MEAN (Bq*Tq*Iq)
#define OFF_STD  (OFF_MEAN + Bq*Zq)

__device__ float g_hf[2][Bq*Hq];
__device__ float g_hb[2][Bq*Hq];
__device__ float g_hd[2][Bq*Hq];
__device__ float g_z[Bq*Zq];
__device__ float g_giz[Bq*G3];
__device__ unsigned g_cnt = 0;
__device__ unsigned g_gen = 0;

struct Smem {
    float As[32][66];        // A transposed [k][m]
    float Ws[3][32][34];     // W transposed [gate][k][n]
    float Xs[64][Iq];
    float Wis[3][32][Iq];
};

__device__ __forceinline__ unsigned long long pk2(float lo, float hi){
    unsigned long long r; asm("mov.b64 %0, {%1,%2};" : "=l"(r) : "f"(lo), "f"(hi)); return r;
}
__device__ __forceinline__ void up2(unsigned long long v, float& lo, float& hi){
    asm("mov.b64 {%0,%1}, %2;" : "=f"(lo), "=f"(hi) : "l"(v));
}
__device__ __forceinline__ void fma2(unsigned long long& a, unsigned long long x, unsigned long long y){
    asm("fma.rn.f32x2 %0, %1, %2, %0;" : "+l"(a) : "l"(x), "l"(y));
}
__device__ __forceinline__ unsigned long long lds2(const float* p){
    return *reinterpret_cast<const unsigned long long*>(p);
}
__device__ __forceinline__ float sgm(float v){ return 1.f/(1.f + expf(-v)); }
__device__ __forceinline__ float wred(float v){
    #pragma unroll
    for (int o = 16; o > 0; o >>= 1) v += __shfl_down_sync(0xffffffffu, v, o);
    return v;
}

__device__ __forceinline__ void gbar(){
    __syncthreads();
    if (threadIdx.x == 0){
        unsigned my = *(volatile unsigned*)&g_gen;
        __threadfence();
        if (atomicAdd(&g_cnt, 1u) == NBLK - 1u){
            atomicExch(&g_cnt, 0u);
            __threadfence();
            atomicAdd(&g_gen, 1u);
        } else {
            while (*(volatile unsigned*)&g_gen == my) __nanosleep(32);
            __threadfence();
        }
    }
    __syncthreads();
}

#define LDGA(K0) { const float* ap_ = hold + (m0+ra)*Hq + (K0) + kaq;                      \
    pa0 = __ldcg((const float4*)ap_); pa1 = __ldcg((const float4*)(ap_+4));                \
    pw0 = __ldg((const float4*)(Whh + (n0+nw)*Hq        + (K0) + kw));                     \
    pw1 = __ldg((const float4*)(Whh + (Hq+n0+nw)*Hq     + (K0) + kw));                     \
    pw2 = __ldg((const float4*)(Whh + (2*Hq+n0+nw)*Hq   + (K0) + kw)); }

template<int DEC>
__device__ __forceinline__ void gru_tile(Smem* sm,
    const float* __restrict__ x, int tt,
    const float* __restrict__ Wih, int ihs,
    const float* __restrict__ Whh,
    const float* __restrict__ bih, const float* __restrict__ bhh,
    const float* __restrict__ hold, float* __restrict__ hnew,
    int m0, int n0)
{
    const int tid = threadIdx.x;
    const int txn = tid & 15, ty = tid >> 4;
    const int j0  = n0 + 2*txn;
    const int ra  = tid & 63, kaq = ((tid >> 6) & 3) * 8;
    const int nw  = tid >> 3, kw  = (tid & 7) * 4;

    __syncthreads();
    for (int idx = tid; idx < 64*Iq; idx += NTHR){
        int r = idx / Iq, c = idx - r*Iq;
        float v;
        if (DEC && tt == 0) v = (c == Iq-1) ? 1.f : 0.f;
        else v = __ldg(&x[(m0 + r)*(Tq*Iq) + (DEC ? tt-1 : tt)*Iq + c]);
        sm->Xs[r][c] = v;
    }
    for (int idx = tid; idx < 3*32*Iq; idx += NTHR){
        int g = idx / (32*Iq); int rem = idx - g*32*Iq; int n = rem / Iq, c = rem - n*Iq;
        sm->Wis[g][n][c] = __ldg(&Wih[(g*Hq + n0 + n)*ihs + c]);
    }

    unsigned long long accr[4], accz[4], accn[4], ginx[4];
    #pragma unroll
    for (int i = 0; i < 4; i++){ accr[i]=0ull; accz[i]=0ull; accn[i]=0ull; ginx[i]=0ull; }

    float4 pa0, pa1, pw0, pw1, pw2;
    LDGA(0);

    for (int kb = 0; kb < 32; kb++){
        __syncthreads();
        sm->As[kaq+0][ra]=pa0.x; sm->As[kaq+1][ra]=pa0.y; sm->As[kaq+2][ra]=pa0.z; sm->As[kaq+3][ra]=pa0.w;
        sm->As[kaq+4][ra]=pa1.x; sm->As[kaq+5][ra]=pa1.y; sm->As[kaq+6][ra]=pa1.z; sm->As[kaq+7][ra]=pa1.w;
        sm->Ws[0][kw+0][nw]=pw0.x; sm->Ws[0][kw+1][nw]=pw0.y; sm->Ws[0][kw+2][nw]=pw0.z; sm->Ws[0][kw+3][nw]=pw0.w;
        sm->Ws[1][kw+0][nw]=pw1.x; sm->Ws[1][kw+1][nw]=pw1.y; sm->Ws[1][kw+2][nw]=pw1.z; sm->Ws[1][kw+3][nw]=pw1.w;
        sm->Ws[2][kw+0][nw]=pw2.x; sm->Ws[2][kw+1][nw]=pw2.y; sm->Ws[2][kw+2][nw]=pw2.z; sm->Ws[2][kw+3][nw]=pw2.w;
        __syncthreads();
        if (kb < 31) LDGA((kb+1)*32);
        #pragma unroll 8
        for (int k = 0; k < 32; k++){
            unsigned long long a01 = lds2(&sm->As[k][ty*4]);
            unsigned long long a23 = lds2(&sm->As[k][ty*4+2]);
            unsigned long long wr  = lds2(&sm->Ws[0][k][2*txn]);
            unsigned long long wz  = lds2(&sm->Ws[1][k][2*txn]);
            unsigned long long wn  = lds2(&sm->Ws[2][k][2*txn]);
            float a0,a1,a2,a3; up2(a01,a0,a1); up2(a23,a2,a3);
            unsigned long long b;
            b=pk2(a0,a0); fma2(accr[0],b,wr); fma2(accz[0],b,wz); fma2(accn[0],b,wn);
            b=pk2(a1,a1); fma2(accr[1],b,wr); fma2(accz[1],b,wz); fma2(accn[1],b,wn);
            b=pk2(a2,a2); fma2(accr[2],b,wr); fma2(accz[2],b,wz); fma2(accn[2],b,wn);
            b=pk2(a3,a3); fma2(accr[3],b,wr); fma2(accz[3],b,wz); fma2(accn[3],b,wn);
        }
    }

    #pragma unroll
    for (int c = 0; c < Iq; c++){
        unsigned long long wr = pk2(sm->Wis[0][2*txn][c], sm->Wis[0][2*txn+1][c]);
        unsigned long long wz = pk2(sm->Wis[1][2*txn][c], sm->Wis[1][2*txn+1][c]);
        unsigned long long wn = pk2(sm->Wis[2][2*txn][c], sm->Wis[2][2*txn+1][c]);
        #pragma unroll
        for (int r = 0; r < 4; r++){
            float xv = sm->Xs[ty*4 + r][c];
            unsigned long long b = pk2(xv, xv);
            fma2(accr[r], b, wr); fma2(accz[r], b, wz); fma2(ginx[r], b, wn);
        }
    }

    float cr0 = __ldg(&bhh[j0]),        cr1 = __ldg(&bhh[j0+1]);
    float cz0 = __ldg(&bhh[Hq+j0]),     cz1 = __ldg(&bhh[Hq+j0+1]);
    float cn0 = __ldg(&bhh[2*Hq+j0]),   cn1 = __ldg(&bhh[2*Hq+j0+1]);
    float br0=0, br1=0, bz0=0, bz1=0, bn0=0, bn1=0;
    if (!DEC){
        br0 = __ldg(&bih[j0]);      br1 = __ldg(&bih[j0+1]);
        bz0 = __ldg(&bih[Hq+j0]);   bz1 = __ldg(&bih[Hq+j0+1]);
        bn0 = __ldg(&bih[2*Hq+j0]); bn1 = __ldg(&bih[2*Hq+j0+1]);
    }

    #pragma unroll
    for (int r = 0; r < 4; r++){
        int m = m0 + ty*4 + r;
        float gr0=br0, gr1=br1, gz0_=bz0, gz1_=bz1, gn0=bn0, gn1=bn1;
        if (DEC){
            float2 t1 = __ldcg((const float2*)&g_giz[m*G3 + j0]);
            float2 t2 = __ldcg((const float2*)&g_giz[m*G3 + Hq + j0]);
            float2 t3 = __ldcg((const float2*)&g_giz[m*G3 + 2*Hq + j0]);
            gr0=t1.x; gr1=t1.y; gz0_=t2.x; gz1_=t2.y; gn0=t3.x; gn1=t3.y;
        }
        float sr0,sr1,sz0,sz1,sn0,sn1,gx0,gx1;
        up2(accr[r],sr0,sr1); up2(accz[r],sz0,sz1); up2(accn[r],sn0,sn1); up2(ginx[r],gx0,gx1);
        float rr0 = sgm(sr0 + gr0 + cr0);
        float rr1 = sgm(sr1 + gr1 + cr1);
        float zz0 = sgm(sz0 + gz0_ + cz0);
        float zz1 = sgm(sz1 + gz1_ + cz1);
        float nn0 = tanhf(gx0 + gn0 + rr0*(sn0 + cn0));
        float nn1 = tanhf(gx1 + gn1 + rr1*(sn1 + cn1));
        float2 ho = __ldcg((const float2*)&hold[m*Hq + j0]);
        float2 res;
        res.x = (1.f - zz0)*nn0 + zz0*ho.x;
        res.y = (1.f - zz1)*nn1 + zz1*ho.y;
        *reinterpret_cast<float2*>(&hnew[m*Hq + j0]) = res;
    }
}

__global__ void __launch_bounds__(NTHR, 1) vae_kernel(
    const float* __restrict__ x, const float* __restrict__ noise,
    const float* __restrict__ Wih_f, const float* __restrict__ Whh_f,
    const float* __restrict__ bih_f, const float* __restrict__ bhh_f,
    const float* __restrict__ Wih_b, const float* __restrict__ Whh_b,
    const float* __restrict__ bih_b, const float* __restrict__ bhh_b,
    const float* __restrict__ Wmu,  const float* __restrict__ bmu,
    const float* __restrict__ Wvar, const float* __restrict__ bvar,
    const float* __restrict__ Winit,const float* __restrict__ binit,
    const float* __restrict__ Wout, const float* __restrict__ bout,
    const float* __restrict__ Wcih, const float* __restrict__ Wchh,
    const float* __restrict__ bcih, const float* __restrict__ bchh,
    float* __restrict__ out)
{
    __shared__ Smem sm;
    const int blk = blockIdx.x, tid = threadIdx.x;
    const int lane = tid & 31;
    const int gwp = blk*8 + (tid >> 5);   // 0..1023

    for (int i = blk*NTHR + tid; i < Bq*Hq; i += NBLK*NTHR){
        g_hf[0][i] = 0.f; g_hb[0][i] = 0.f;
    }
    gbar();

    // ---- encoder ----
    for (int t = 0; t < Tq; t++){
        int par = t & 1;
        #pragma unroll 1
        for (int half = 0; half < 2; half++){
            int tile = blk + half*NBLK;     // 0..255
            int dir = tile >> 7, r2 = tile & 127;
            int m0 = (r2 >> 5) * 64, n0 = (r2 & 31) * 32;
            int tt = dir ? (Tq - 1 - t) : t;
            if (dir == 0)
                gru_tile<0>(&sm, x, tt, Wih_f, Iq, Whh_f, bih_f, bhh_f,
                            g_hf[par], g_hf[par^1], m0, n0);
            else
                gru_tile<0>(&sm, x, tt, Wih_b, Iq, Whh_b, bih_b, bhh_b,
                            g_hb[par], g_hb[par^1], m0, n0);
        }
        gbar();
    }

    // ---- heads: mean / std / z ----
    for (int it = gwp; it < Bq*Zq; it += 1024){
        int m = it >> 7, zi = it & 127;
        const float* hf = &g_hf[0][m*Hq];
        const float* hb = &g_hb[0][m*Hq];
        const float* wm = &Wmu[zi*2*Hq];
        const float* wv = &Wvar[zi*2*Hq];
        float am = 0.f, av = 0.f;
        for (int k = lane; k < Hq; k += 32){
            float h1 = __ldcg(&hf[k]); am += h1*__ldg(&wm[k]);    av += h1*__ldg(&wv[k]);
            float h2 = __ldcg(&hb[k]); am += h2*__ldg(&wm[Hq+k]); av += h2*__ldg(&wv[Hq+k]);
        }
        am = wred(am); av = wred(av);
        if (lane == 0){
            float mean = am + __ldg(&bmu[zi]);
            float sd = expf(0.5f*(av + __ldg(&bvar[zi])));
            out[OFF_MEAN + m*Zq + zi] = mean;
            out[OFF_STD  + m*Zq + zi] = sd;
            g_z[m*Zq + zi] = mean + sd*__ldg(&noise[m*Zq + zi]);
        }
    }
    gbar();

    // ---- giz (z-part of decoder input gates) + hx ----
    for (int it = gwp; it < Bq*G3; it += 1024){
        int m = it / G3, gc = it - m*G3;
        const float* zr = &g_z[m*Zq];
        const float* wr = &Wcih[gc*(Iq + Zq) + Iq];
        float acc = 0.f;
        for (int k = lane; k < Zq; k += 32) acc += __ldcg(&zr[k])*__ldg(&wr[k]);
        acc = wred(acc);
        if (lane == 0) g_giz[m*G3 + gc] = acc + __ldg(&bcih[gc]);
    }
    for (int it = gwp; it < Bq*Hq; it += 1024){
        int m = it >> 10, j = it & 1023;
        const float* zr = &g_z[m*Zq];
        const float* wr = &Winit[j*Zq];
        float acc = 0.f;
        for (int k = lane; k < Zq; k += 32) acc += __ldcg(&zr[k])*__ldg(&wr[k]);
        acc = wred(acc);
        if (lane == 0) g_hd[0][m*Hq + j] = tanhf(acc + __ldg(&binit[j]));
    }
    gbar();

    // ---- decoder ----
    for (int t = 0; t < Tq; t++){
        int par = t & 1;
        if (t > 0){
            // output projection for step t-1 from hold = h(t) (already synced)
            const float* hbuf = g_hd[par];
            #pragma unroll 1
            for (int j = 0; j < 3; j++){
                int it = gwp + j*1024;     // 0..3071
                int m = it / Iq, i = it - m*Iq;
                const float* h = &hbuf[m*Hq];
                const float* w = &Wout[i*Hq];
                float acc = 0.f;
                for (int k = lane; k < Hq; k += 32) acc += __ldcg(&h[k])*__ldg(&w[k]);
                acc = wred(acc);
                if (lane == 0)
                    out[m*(Tq*Iq) + (t-1)*Iq + i] = sgm(acc + __ldg(&bout[i]));
            }
        }
        int m0 = (blk >> 5) * 64, n0 = (blk & 31) * 32;
        gru_tile<1>(&sm, x, t, Wcih, Iq + Zq, Wchh, bcih, bchh,
                    g_hd[par], g_hd[par^1], m0, n0);
        gbar();
    }

    // final output projection for t = Tq-1 from g_hd[0]
    {
        const float* hbuf = g_hd[0];
        #pragma unroll 1
        for (int j = 0; j < 3; j++){
            int it = gwp + j*1024;
            int m = it / Iq, i = it - m*Iq;
            const float* h = &hbuf[m*Hq];
            const float* w = &Wout[i*Hq];
            float acc = 0.f;
            for (int k = lane; k < Hq; k += 32) acc += __ldcg(&h[k])*__ldg(&w[k]);
            acc = wred(acc);
            if (lane == 0)
                out[m*(Tq*Iq) + (Tq-1)*Iq + i] = sgm(acc + __ldg(&bout[i]));
        }
    }
}

extern "C" void kernel_launch(void* const* d_in, const int* in_sizes, int n_in,
                              void* d_out, int out_size)
{
    vae_kernel<<<NBLK, NTHR>>>(
        (const float*)d_in[0],  (const float*)d_in[1],
        (const float*)d_in[2],  (const float*)d_in[3],
        (const float*)d_in[4],  (const float*)d_in[5],
        (const float*)d_in[6],  (const float*)d_in[7],
        (const float*)d_in[8],  (const float*)d_in[9],
        (const float*)d_in[10], (const float*)d_in[11],
        (const float*)d_in[12], (const float*)d_in[13],
        (const float*)d_in[14], (const float*)d_in[15],
        (const float*)d_in[16], (const float*)d_in[17],
        (const float*)d_in[18], (const float*)d_in[19],
        (const float*)d_in[20], (const float*)d_in[21],
        (float*)d_out);
}

// round 5
// speedup vs baseline: 1.0315x; 1.0315x over previous
#include <cuda_runtime.h>
#include <math.h>

#define Bq 256
#define Tq 512
#define Iq 12
#define Hq 1024
#define Zq 128
#define G3 3072
#define NBLK 128
#define NTHR 512
#define NWARP (NBLK*(NTHR/32))
#define OFF_MEAN (Bq*Tq*Iq)
#define OFF_STD  (OFF_MEAN + Bq*Zq)

__device__ float g_hf[2][Bq*Hq];
__device__ float g_hb[2][Bq*Hq];
__device__ float g_hd[2][Bq*Hq];
__device__ float g_z[Bq*Zq];
__device__ float g_giz[Bq*G3];
__device__ unsigned g_cnt = 0;
__device__ unsigned g_gen = 0;

struct Smem {
    float As[32][130];
    float Ws[3][32][34];
    float Xs[128][Iq];
    float Wis[3][32][Iq];
};

__device__ __forceinline__ unsigned long long pk2(float lo, float hi){
    unsigned long long r; asm("mov.b64 %0, {%1,%2};" : "=l"(r) : "f"(lo), "f"(hi)); return r;
}
__device__ __forceinline__ void up2(unsigned long long v, float& lo, float& hi){
    asm("mov.b64 {%0,%1}, %2;" : "=f"(lo), "=f"(hi) : "l"(v));
}
__device__ __forceinline__ void fma2(unsigned long long& a, unsigned long long x, unsigned long long y){
    asm("fma.rn.f32x2 %0, %1, %2, %0;" : "+l"(a) : "l"(x), "l"(y));
}
__device__ __forceinline__ unsigned long long lds2(const float* p){
    return *reinterpret_cast<const unsigned long long*>(p);
}
__device__ __forceinline__ float sgm(float v){ return 1.f/(1.f + expf(-v)); }
__device__ __forceinline__ float wred(float v){
    #pragma unroll
    for (int o = 16; o > 0; o >>= 1) v += __shfl_down_sync(0xffffffffu, v, o);
    return v;
}

__device__ __forceinline__ void gbar(){
    __syncthreads();
    if (threadIdx.x == 0){
        unsigned my = *(volatile unsigned*)&g_gen;
        __threadfence();
        if (atomicAdd(&g_cnt, 1u) == NBLK - 1u){
            atomicExch(&g_cnt, 0u);
            __threadfence();
            atomicAdd(&g_gen, 1u);
        } else {
            while (*(volatile unsigned*)&g_gen == my) __nanosleep(32);
            __threadfence();
        }
    }
    __syncthreads();
}

// MR rows per thread: 4 (BM=128, encoder) or 2 (BM=64, decoder)
template<int MR, int DEC>
__device__ __forceinline__ void gru_tile(Smem* sm,
    const float* __restrict__ x, int tt,
    const float* __restrict__ Wih, int ihs,
    const float* __restrict__ Whh,
    const float* __restrict__ bih, const float* __restrict__ bhh,
    const float* __restrict__ hold, float* __restrict__ hnew,
    int m0, int n0)
{
    const int BM = MR*32, NF4A = BM/64;     // float4s per thread for A
    const int tid = threadIdx.x;
    const int txn = tid & 15, ty = tid >> 4;
    const int j0  = n0 + 2*txn;
    const int arow = (NF4A==2) ? (tid>>2) : (tid>>3);
    const int ak   = (NF4A==2) ? ((tid&3)*8) : ((tid&7)*4);
    const int wrow = tid >> 2;              // 0..95 valid (tid<384)
    const int wg = wrow >> 5, wn = wrow & 31, wk = (tid&3)*8;

    __syncthreads();
    for (int idx = tid; idx < BM*Iq; idx += NTHR){
        int r = idx / Iq, c = idx - r*Iq;
        float v;
        if (DEC && tt == 0) v = (c == Iq-1) ? 1.f : 0.f;
        else v = __ldg(&x[(m0 + r)*(Tq*Iq) + (DEC ? tt-1 : tt)*Iq + c]);
        sm->Xs[r][c] = v;
    }
    for (int idx = tid; idx < 3*32*Iq; idx += NTHR){
        int g = idx / (32*Iq); int rem = idx - g*32*Iq; int n = rem / Iq, c = rem - n*Iq;
        sm->Wis[g][n][c] = __ldg(&Wih[(g*Hq + n0 + n)*ihs + c]);
    }

    unsigned long long accr[MR], accz[MR], accn[MR], ginx[MR];
    #pragma unroll
    for (int i = 0; i < MR; i++){ accr[i]=0ull; accz[i]=0ull; accn[i]=0ull; ginx[i]=0ull; }

    float4 pa[2], pw[2];
    const float* abase = hold + (m0 + arow)*Hq + ak;
    const float* wbase = (tid < 384) ? (Whh + (wg*Hq + n0 + wn)*Hq + wk) : Whh;
    #pragma unroll
    for (int q = 0; q < NF4A; q++) pa[q] = __ldcg((const float4*)(abase + 4*q));
    pw[0] = __ldg((const float4*)wbase); pw[1] = __ldg((const float4*)(wbase + 4));

    for (int kb = 0; kb < 32; kb++){
        __syncthreads();
        #pragma unroll
        for (int q = 0; q < NF4A; q++){
            int kk = ak + 4*q;
            sm->As[kk+0][arow]=pa[q].x; sm->As[kk+1][arow]=pa[q].y;
            sm->As[kk+2][arow]=pa[q].z; sm->As[kk+3][arow]=pa[q].w;
        }
        if (tid < 384){
            sm->Ws[wg][wk+0][wn]=pw[0].x; sm->Ws[wg][wk+1][wn]=pw[0].y;
            sm->Ws[wg][wk+2][wn]=pw[0].z; sm->Ws[wg][wk+3][wn]=pw[0].w;
            sm->Ws[wg][wk+4][wn]=pw[1].x; sm->Ws[wg][wk+5][wn]=pw[1].y;
            sm->Ws[wg][wk+6][wn]=pw[1].z; sm->Ws[wg][wk+7][wn]=pw[1].w;
        }
        __syncthreads();
        if (kb < 31){
            int ko = (kb+1)*32;
            #pragma unroll
            for (int q = 0; q < NF4A; q++) pa[q] = __ldcg((const float4*)(abase + ko + 4*q));
            pw[0] = __ldg((const float4*)(wbase + ko)); pw[1] = __ldg((const float4*)(wbase + ko + 4));
        }
        #pragma unroll 8
        for (int k = 0; k < 32; k++){
            unsigned long long wr = lds2(&sm->Ws[0][k][2*txn]);
            unsigned long long wz = lds2(&sm->Ws[1][k][2*txn]);
            unsigned long long wn2 = lds2(&sm->Ws[2][k][2*txn]);
            float av[MR];
            {
                float l0,l1; up2(lds2(&sm->As[k][ty*MR]), l0, l1);
                av[0]=l0; av[1]=l1;
                if (MR==4){ float l2,l3; up2(lds2(&sm->As[k][ty*MR+2]), l2, l3); av[2]=l2; av[3]=l3; }
            }
            #pragma unroll
            for (int r = 0; r < MR; r++){
                unsigned long long b = pk2(av[r], av[r]);
                fma2(accr[r],b,wr); fma2(accz[r],b,wz); fma2(accn[r],b,wn2);
            }
        }
    }

    #pragma unroll
    for (int c = 0; c < Iq; c++){
        unsigned long long wr = pk2(sm->Wis[0][2*txn][c], sm->Wis[0][2*txn+1][c]);
        unsigned long long wz = pk2(sm->Wis[1][2*txn][c], sm->Wis[1][2*txn+1][c]);
        unsigned long long wn2 = pk2(sm->Wis[2][2*txn][c], sm->Wis[2][2*txn+1][c]);
        #pragma unroll
        for (int r = 0; r < MR; r++){
            float xv = sm->Xs[ty*MR + r][c];
            unsigned long long b = pk2(xv, xv);
            fma2(accr[r],b,wr); fma2(accz[r],b,wz); fma2(ginx[r],b,wn2);
        }
    }

    float cr0 = __ldg(&bhh[j0]),      cr1 = __ldg(&bhh[j0+1]);
    float cz0 = __ldg(&bhh[Hq+j0]),   cz1 = __ldg(&bhh[Hq+j0+1]);
    float cn0 = __ldg(&bhh[2*Hq+j0]), cn1 = __ldg(&bhh[2*Hq+j0+1]);
    float br0=0,br1=0,bz0=0,bz1=0,bn0=0,bn1=0;
    if (!DEC){
        br0=__ldg(&bih[j0]);      br1=__ldg(&bih[j0+1]);
        bz0=__ldg(&bih[Hq+j0]);   bz1=__ldg(&bih[Hq+j0+1]);
        bn0=__ldg(&bih[2*Hq+j0]); bn1=__ldg(&bih[2*Hq+j0+1]);
    }

    #pragma unroll
    for (int r = 0; r < MR; r++){
        int m = m0 + ty*MR + r;
        float gr0=br0,gr1=br1,gz0=bz0,gz1=bz1,gn0=bn0,gn1=bn1;
        if (DEC){
            float2 t1 = __ldcg((const float2*)&g_giz[m*G3 + j0]);
            float2 t2 = __ldcg((const float2*)&g_giz[m*G3 + Hq + j0]);
            float2 t3 = __ldcg((const float2*)&g_giz[m*G3 + 2*Hq + j0]);
            gr0=t1.x; gr1=t1.y; gz0=t2.x; gz1=t2.y; gn0=t3.x; gn1=t3.y;
        }
        float sr0,sr1,sz0,sz1,sn0,sn1,gx0,gx1;
        up2(accr[r],sr0,sr1); up2(accz[r],sz0,sz1); up2(accn[r],sn0,sn1); up2(ginx[r],gx0,gx1);
        float rr0 = sgm(sr0+gr0+cr0), rr1 = sgm(sr1+gr1+cr1);
        float zz0 = sgm(sz0+gz0+cz0), zz1 = sgm(sz1+gz1+cz1);
        float nn0 = tanhf(gx0+gn0 + rr0*(sn0+cn0));
        float nn1 = tanhf(gx1+gn1 + rr1*(sn1+cn1));
        float2 ho = __ldcg((const float2*)&hold[m*Hq + j0]);
        float2 res;
        res.x = (1.f-zz0)*nn0 + zz0*ho.x;
        res.y = (1.f-zz1)*nn1 + zz1*ho.y;
        *reinterpret_cast<float2*>(&hnew[m*Hq + j0]) = res;
    }
}

__global__ void __launch_bounds__(NTHR, 1) vae_kernel(
    const float* __restrict__ x, const float* __restrict__ noise,
    const float* __restrict__ Wih_f, const float* __restrict__ Whh_f,
    const float* __restrict__ bih_f, const float* __restrict__ bhh_f,
    const float* __restrict__ Wih_b, const float* __restrict__ Whh_b,
    const float* __restrict__ bih_b, const float* __restrict__ bhh_b,
    const float* __restrict__ Wmu,  const float* __restrict__ bmu,
    const float* __restrict__ Wvar, const float* __restrict__ bvar,
    const float* __restrict__ Winit,const float* __restrict__ binit,
    const float* __restrict__ Wout, const float* __restrict__ bout,
    const float* __restrict__ Wcih, const float* __restrict__ Wchh,
    const float* __restrict__ bcih, const float* __restrict__ bchh,
    float* __restrict__ out)
{
    __shared__ Smem sm;
    const int blk = blockIdx.x, tid = threadIdx.x;
    const int lane = tid & 31;
    const int gwp = blk*16 + (tid >> 5);   // 0..2047

    for (int i = blk*NTHR + tid; i < Bq*Hq; i += NBLK*NTHR){
        g_hf[0][i] = 0.f; g_hb[0][i] = 0.f;
    }
    gbar();

    // encoder: 128 tiles = 2 m-tiles x 32 n-tiles x 2 dirs
    const int edir = blk >> 6, erem = blk & 63;
    const int em0 = (erem >> 5)*128, en0 = (erem & 31)*32;
    for (int t = 0; t < Tq; t++){
        int par = t & 1;
        if (edir == 0)
            gru_tile<4,0>(&sm, x, t, Wih_f, Iq, Whh_f, bih_f, bhh_f,
                          g_hf[par], g_hf[par^1], em0, en0);
        else
            gru_tile<4,0>(&sm, x, Tq-1-t, Wih_b, Iq, Whh_b, bih_b, bhh_b,
                          g_hb[par], g_hb[par^1], em0, en0);
        gbar();
    }

    // heads
    for (int it = gwp; it < Bq*Zq; it += NWARP/1){
        int m = it >> 7, zi = it & 127;
        const float* hf = &g_hf[0][m*Hq];
        const float* hb = &g_hb[0][m*Hq];
        const float* wm = &Wmu[zi*2*Hq];
        const float* wv = &Wvar[zi*2*Hq];
        float am = 0.f, av = 0.f;
        for (int k = lane; k < Hq; k += 32){
            float h1 = __ldcg(&hf[k]); am += h1*__ldg(&wm[k]);    av += h1*__ldg(&wv[k]);
            float h2 = __ldcg(&hb[k]); am += h2*__ldg(&wm[Hq+k]); av += h2*__ldg(&wv[Hq+k]);
        }
        am = wred(am); av = wred(av);
        if (lane == 0){
            float mean = am + __ldg(&bmu[zi]);
            float sd = expf(0.5f*(av + __ldg(&bvar[zi])));
            out[OFF_MEAN + m*Zq + zi] = mean;
            out[OFF_STD  + m*Zq + zi] = sd;
            g_z[m*Zq + zi] = mean + sd*__ldg(&noise[m*Zq + zi]);
        }
    }
    gbar();

    // giz + hx
    for (int it = gwp; it < Bq*G3; it += NWARP){
        int m = it / G3, gc = it - m*G3;
        const float* zr = &g_z[m*Zq];
        const float* wr = &Wcih[gc*(Iq + Zq) + Iq];
        float acc = 0.f;
        for (int k = lane; k < Zq; k += 32) acc += __ldcg(&zr[k])*__ldg(&wr[k]);
        acc = wred(acc);
        if (lane == 0) g_giz[m*G3 + gc] = acc + __ldg(&bcih[gc]);
    }
    for (int it = gwp; it < Bq*Hq; it += NWARP){
        int m = it >> 10, j = it & 1023;
        const float* zr = &g_z[m*Zq];
        const float* wr = &Winit[j*Zq];
        float acc = 0.f;
        for (int k = lane; k < Zq; k += 32) acc += __ldcg(&zr[k])*__ldg(&wr[k]);
        acc = wred(acc);
        if (lane == 0) g_hd[0][m*Hq + j] = tanhf(acc + __ldg(&binit[j]));
    }
    gbar();

    // decoder: 128 tiles = 4 m-tiles x 32 n-tiles
    const int dm0 = (blk >> 5)*64, dn0 = (blk & 31)*32;
    for (int t = 0; t < Tq; t++){
        int par = t & 1;
        if (t > 0){
            const float* hbuf = g_hd[par];
            for (int it = gwp; it < Bq*Iq; it += NWARP){
                int m = it / Iq, i = it - m*Iq;
                const float* h = &hbuf[m*Hq];
                const float* w = &Wout[i*Hq];
                float acc = 0.f;
                for (int k = lane; k < Hq; k += 32) acc += __ldcg(&h[k])*__ldg(&w[k]);
                acc = wred(acc);
                if (lane == 0)
                    out[m*(Tq*Iq) + (t-1)*Iq + i] = sgm(acc + __ldg(&bout[i]));
            }
        }
        gru_tile<2,1>(&sm, x, t, Wcih, Iq + Zq, Wchh, bcih, bchh,
                      g_hd[par], g_hd[par^1], dm0, dn0);
        gbar();
    }

    {
        const float* hbuf = g_hd[0];
        for (int it = gwp; it < Bq*Iq; it += NWARP){
            int m = it / Iq, i = it - m*Iq;
            const float* h = &hbuf[m*Hq];
            const float* w = &Wout[i*Hq];
            float acc = 0.f;
            for (int k = lane; k < Hq; k += 32) acc += __ldcg(&h[k])*__ldg(&w[k]);
            acc = wred(acc);
            if (lane == 0)
                out[m*(Tq*Iq) + (Tq-1)*Iq + i] = sgm(acc + __ldg(&bout[i]));
        }
    }
}

extern "C" void kernel_launch(void* const* d_in, const int* in_sizes, int n_in,
                              void* d_out, int out_size)
{
    vae_kernel<<<NBLK, NTHR>>>(
        (const float*)d_in[0],  (const float*)d_in[1],
        (const float*)d_in[2],  (const float*)d_in[3],
        (const float*)d_in[4],  (const float*)d_in[5],
        (const float*)d_in[6],  (const float*)d_in[7],
        (const float*)d_in[8],  (const float*)d_in[9],
        (const float*)d_in[10], (const float*)d_in[11],
        (const float*)d_in[12], (const float*)d_in[13],
        (const float*)d_in[14], (const float*)d_in[15],
        (const float*)d_in[16], (const float*)d_in[17],
        (const float*)d_in[18], (const float*)d_in[19],
        (const float*)d_in[20], (const float*)d_in[21],
        (float*)d_out);
}

// round 6
// speedup vs baseline: 1.9846x; 1.9240x over previous
#include <cuda_runtime.h>
#include <math.h>

#define Bq 256
#define Tq 512
#define Iq 12
#define Hq 1024
#define Zq 128
#define G3 3072
#define NBLK 128
#define NTHR 512
#define NWARP 2048
#define OFF_MEAN (Bq*Tq*Iq)
#define OFF_STD  (OFF_MEAN + Bq*Zq)

__device__ float g_hf[2][Bq*Hq];
__device__ float g_hb[2][Bq*Hq];
__device__ float g_hd[2][Bq*Hq];
__device__ float g_z[Bq*Zq];
__device__ float g_giz[Bq*G3];
__device__ unsigned g_cnt = 0;
__device__ unsigned g_gen = 0;

struct Smem {
    float As[32][132];       // [k][m], stride 132 (16B aligned, conflict-free)
    float Ws[3][32][33];     // [gate][k][n]
    float Xs[128][Iq];
    float Wis[3][32][Iq];
};

__device__ __forceinline__ unsigned long long pk2(float lo, float hi){
    unsigned long long r; asm("mov.b64 %0, {%1,%2};" : "=l"(r) : "f"(lo), "f"(hi)); return r;
}
__device__ __forceinline__ void up2(unsigned long long v, float& lo, float& hi){
    asm("mov.b64 {%0,%1}, %2;" : "=f"(lo), "=f"(hi) : "l"(v));
}
__device__ __forceinline__ void fma2(unsigned long long& a, unsigned long long x, unsigned long long y){
    asm("fma.rn.f32x2 %0, %1, %2, %0;" : "+l"(a) : "l"(x), "l"(y));
}
__device__ __forceinline__ float sgm(float v){ return 1.f/(1.f + expf(-v)); }
__device__ __forceinline__ float wred(float v){
    #pragma unroll
    for (int o = 16; o > 0; o >>= 1) v += __shfl_down_sync(0xffffffffu, v, o);
    return v;
}

__device__ __forceinline__ void gbar(){
    __syncthreads();
    if (threadIdx.x == 0){
        unsigned my = *(volatile unsigned*)&g_gen;
        __threadfence();
        if (atomicAdd(&g_cnt, 1u) == NBLK - 1u){
            atomicExch(&g_cnt, 0u);
            __threadfence();
            atomicAdd(&g_gen, 1u);
        } else {
            while (*(volatile unsigned*)&g_gen == my) __nanosleep(32);
            __threadfence();
        }
    }
    __syncthreads();
}

// One scalar output column j for row m: gate math + h update
template<int DEC>
__device__ __forceinline__ void emit(float sr, float sz, float sn, float gx,
    int m, int j, float br, float bz, float bn, float cr, float cz, float cn,
    const float* __restrict__ hold, float* __restrict__ hnew)
{
    float gr = br, gz = bz, gn = bn;
    if (DEC){
        gr = __ldcg(&g_giz[m*G3 + j]);
        gz = __ldcg(&g_giz[m*G3 + Hq + j]);
        gn = __ldcg(&g_giz[m*G3 + 2*Hq + j]);
    }
    float rr = sgm(sr + gr + cr);
    float zz = sgm(sz + gz + cz);
    float nn = tanhf(gx + gn + rr*(sn + cn));
    float ho = __ldcg(&hold[m*Hq + j]);
    hnew[m*Hq + j] = (1.f - zz)*nn + zz*ho;
}

// MR rows/thread (8 -> BM=128 encoder, 4 -> BM=64 decoder); f32x2 packs M-row pairs.
template<int MR, int DEC>
__device__ __forceinline__ void gru_tile(Smem* sm,
    const float* __restrict__ x, int tt,
    const float* __restrict__ Wih, int ihs,
    const float* __restrict__ Whh,
    const float* __restrict__ bih, const float* __restrict__ bhh,
    const float* __restrict__ hold, float* __restrict__ hnew,
    int m0, int n0)
{
    const int BM = MR*16, NR = BM/16, NP = MR/2;
    const int tid = threadIdx.x;
    const int tx = tid & 31, ty = tid >> 5;
    const int mr0 = ty*MR;
    const int j = n0 + tx;
    const int lane = tx, ar0 = ty*NR;               // A staging: lane = k
    const int wrow = tid >> 2;                      // W staging (tid < 384)
    const int wg = wrow >> 5, wn = wrow & 31, wk = (tid & 3)*8;

    __syncthreads();
    for (int idx = tid; idx < BM*Iq; idx += NTHR){
        int r = idx/Iq, c = idx - r*Iq;
        float v;
        if (DEC && tt == 0) v = (c == Iq-1) ? 1.f : 0.f;
        else v = __ldg(&x[(m0 + r)*(Tq*Iq) + (DEC ? tt-1 : tt)*Iq + c]);
        sm->Xs[r][c] = v;
    }
    for (int idx = tid; idx < 3*32*Iq; idx += NTHR){
        int g = idx/(32*Iq); int rem = idx - g*32*Iq; int n = rem/Iq, c = rem - n*Iq;
        sm->Wis[g][n][c] = __ldg(&Wih[(g*Hq + n0 + n)*ihs + c]);
    }

    unsigned long long accr[NP], accz[NP], accn[NP], ginx[NP];
    #pragma unroll
    for (int i = 0; i < NP; i++){ accr[i]=0ull; accz[i]=0ull; accn[i]=0ull; ginx[i]=0ull; }

    float pa[8]; float4 pw0, pw1;
    const float* ab = hold + (m0 + ar0)*Hq + lane;
    const float* wb = (tid < 384) ? (Whh + (wg*Hq + n0 + wn)*Hq + wk) : Whh;
    #pragma unroll
    for (int r = 0; r < NR; r++) pa[r] = __ldcg(ab + r*Hq);
    pw0 = __ldg((const float4*)wb); pw1 = __ldg((const float4*)(wb + 4));

    for (int kb = 0; kb < 32; kb++){
        __syncthreads();
        #pragma unroll
        for (int q = 0; q < NR/4; q++)
            *(float4*)&sm->As[lane][ar0 + 4*q] =
                make_float4(pa[4*q], pa[4*q+1], pa[4*q+2], pa[4*q+3]);
        if (tid < 384){
            sm->Ws[wg][wk+0][wn]=pw0.x; sm->Ws[wg][wk+1][wn]=pw0.y;
            sm->Ws[wg][wk+2][wn]=pw0.z; sm->Ws[wg][wk+3][wn]=pw0.w;
            sm->Ws[wg][wk+4][wn]=pw1.x; sm->Ws[wg][wk+5][wn]=pw1.y;
            sm->Ws[wg][wk+6][wn]=pw1.z; sm->Ws[wg][wk+7][wn]=pw1.w;
        }
        __syncthreads();
        if (kb < 31){
            int ko = (kb+1)*32;
            #pragma unroll
            for (int r = 0; r < NR; r++) pa[r] = __ldcg(ab + ko + r*Hq);
            pw0 = __ldg((const float4*)(wb + ko)); pw1 = __ldg((const float4*)(wb + ko + 4));
        }
        #pragma unroll 8
        for (int k = 0; k < 32; k++){
            float w0 = sm->Ws[0][k][tx], w1 = sm->Ws[1][k][tx], w2 = sm->Ws[2][k][tx];
            unsigned long long wr = pk2(w0,w0), wz = pk2(w1,w1), wn2 = pk2(w2,w2);
            ulonglong2 a0 = *(const ulonglong2*)&sm->As[k][mr0];
            fma2(accr[0],a0.x,wr); fma2(accz[0],a0.x,wz); fma2(accn[0],a0.x,wn2);
            fma2(accr[1],a0.y,wr); fma2(accz[1],a0.y,wz); fma2(accn[1],a0.y,wn2);
            if (MR == 8){
                ulonglong2 a1 = *(const ulonglong2*)&sm->As[k][mr0 + 4];
                fma2(accr[2],a1.x,wr); fma2(accz[2],a1.x,wz); fma2(accn[2],a1.x,wn2);
                fma2(accr[3],a1.y,wr); fma2(accz[3],a1.y,wz); fma2(accn[3],a1.y,wn2);
            }
        }
    }

    #pragma unroll
    for (int c = 0; c < Iq; c++){
        float w0 = sm->Wis[0][tx][c], w1 = sm->Wis[1][tx][c], w2 = sm->Wis[2][tx][c];
        unsigned long long wr = pk2(w0,w0), wz = pk2(w1,w1), wn2 = pk2(w2,w2);
        #pragma unroll
        for (int p = 0; p < NP; p++){
            unsigned long long b = pk2(sm->Xs[mr0+2*p][c], sm->Xs[mr0+2*p+1][c]);
            fma2(accr[p],b,wr); fma2(accz[p],b,wz); fma2(ginx[p],b,wn2);
        }
    }

    float cr = __ldg(&bhh[j]), cz = __ldg(&bhh[Hq+j]), cn = __ldg(&bhh[2*Hq+j]);
    float br = 0, bz = 0, bn = 0;
    if (!DEC){ br = __ldg(&bih[j]); bz = __ldg(&bih[Hq+j]); bn = __ldg(&bih[2*Hq+j]); }

    #pragma unroll
    for (int p = 0; p < NP; p++){
        float sr0,sr1,sz0,sz1,sn0,sn1,gx0,gx1;
        up2(accr[p],sr0,sr1); up2(accz[p],sz0,sz1); up2(accn[p],sn0,sn1); up2(ginx[p],gx0,gx1);
        int m = m0 + mr0 + 2*p;
        emit<DEC>(sr0,sz0,sn0,gx0, m,   j, br,bz,bn, cr,cz,cn, hold, hnew);
        emit<DEC>(sr1,sz1,sn1,gx1, m+1, j, br,bz,bn, cr,cz,cn, hold, hnew);
    }
}

__global__ void __launch_bounds__(NTHR, 1) vae_kernel(
    const float* __restrict__ x, const float* __restrict__ noise,
    const float* __restrict__ Wih_f, const float* __restrict__ Whh_f,
    const float* __restrict__ bih_f, const float* __restrict__ bhh_f,
    const float* __restrict__ Wih_b, const float* __restrict__ Whh_b,
    const float* __restrict__ bih_b, const float* __restrict__ bhh_b,
    const float* __restrict__ Wmu,  const float* __restrict__ bmu,
    const float* __restrict__ Wvar, const float* __restrict__ bvar,
    const float* __restrict__ Winit,const float* __restrict__ binit,
    const float* __restrict__ Wout, const float* __restrict__ bout,
    const float* __restrict__ Wcih, const float* __restrict__ Wchh,
    const float* __restrict__ bcih, const float* __restrict__ bchh,
    float* __restrict__ out)
{
    __shared__ Smem sm;
    const int blk = blockIdx.x, tid = threadIdx.x;
    const int lane = tid & 31;
    const int gwp = blk*16 + (tid >> 5);

    for (int i = blk*NTHR + tid; i < Bq*Hq; i += NBLK*NTHR){
        g_hf[0][i] = 0.f; g_hb[0][i] = 0.f;
    }
    gbar();

    const int edir = blk >> 6, erem = blk & 63;
    const int em0 = (erem >> 5)*128, en0 = (erem & 31)*32;
    for (int t = 0; t < Tq; t++){
        int par = t & 1;
        if (edir == 0)
            gru_tile<8,0>(&sm, x, t, Wih_f, Iq, Whh_f, bih_f, bhh_f,
                          g_hf[par], g_hf[par^1], em0, en0);
        else
            gru_tile<8,0>(&sm, x, Tq-1-t, Wih_b, Iq, Whh_b, bih_b, bhh_b,
                          g_hb[par], g_hb[par^1], em0, en0);
        gbar();
    }

    for (int it = gwp; it < Bq*Zq; it += NWARP){
        int m = it >> 7, zi = it & 127;
        const float* hf = &g_hf[0][m*Hq];
        const float* hb = &g_hb[0][m*Hq];
        const float* wm = &Wmu[zi*2*Hq];
        const float* wv = &Wvar[zi*2*Hq];
        float am = 0.f, av = 0.f;
        for (int k = lane; k < Hq; k += 32){
            float h1 = __ldcg(&hf[k]); am += h1*__ldg(&wm[k]);    av += h1*__ldg(&wv[k]);
            float h2 = __ldcg(&hb[k]); am += h2*__ldg(&wm[Hq+k]); av += h2*__ldg(&wv[Hq+k]);
        }
        am = wred(am); av = wred(av);
        if (lane == 0){
            float mean = am + __ldg(&bmu[zi]);
            float sd = expf(0.5f*(av + __ldg(&bvar[zi])));
            out[OFF_MEAN + m*Zq + zi] = mean;
            out[OFF_STD  + m*Zq + zi] = sd;
            g_z[m*Zq + zi] = mean + sd*__ldg(&noise[m*Zq + zi]);
        }
    }
    gbar();

    for (int it = gwp; it < Bq*G3; it += NWARP){
        int m = it / G3, gc = it - m*G3;
        const float* zr = &g_z[m*Zq];
        const float* wr = &Wcih[gc*(Iq + Zq) + Iq];
        float acc = 0.f;
        for (int k = lane; k < Zq; k += 32) acc += __ldcg(&zr[k])*__ldg(&wr[k]);
        acc = wred(acc);
        if (lane == 0) g_giz[m*G3 + gc] = acc + __ldg(&bcih[gc]);
    }
    for (int it = gwp; it < Bq*Hq; it += NWARP){
        int m = it >> 10, jj = it & 1023;
        const float* zr = &g_z[m*Zq];
        const float* wr = &Winit[jj*Zq];
        float acc = 0.f;
        for (int k = lane; k < Zq; k += 32) acc += __ldcg(&zr[k])*__ldg(&wr[k]);
        acc = wred(acc);
        if (lane == 0) g_hd[0][m*Hq + jj] = tanhf(acc + __ldg(&binit[jj]));
    }
    gbar();

    const int dm0 = (blk >> 5)*64, dn0 = (blk & 31)*32;
    for (int t = 0; t < Tq; t++){
        int par = t & 1;
        if (t > 0){
            const float* hbuf = g_hd[par];
            for (int it = gwp; it < Bq*Iq; it += NWARP){
                int m = it / Iq, i = it - m*Iq;
                const float* h = &hbuf[m*Hq];
                const float* w = &Wout[i*Hq];
                float acc = 0.f;
                for (int k = lane; k < Hq; k += 32) acc += __ldcg(&h[k])*__ldg(&w[k]);
                acc = wred(acc);
                if (lane == 0)
                    out[m*(Tq*Iq) + (t-1)*Iq + i] = sgm(acc + __ldg(&bout[i]));
            }
        }
        gru_tile<4,1>(&sm, x, t, Wcih, Iq + Zq, Wchh, bcih, bchh,
                      g_hd[par], g_hd[par^1], dm0, dn0);
        gbar();
    }

    {
        const float* hbuf = g_hd[0];
        for (int it = gwp; it < Bq*Iq; it += NWARP){
            int m = it / Iq, i = it - m*Iq;
            const float* h = &hbuf[m*Hq];
            const float* w = &Wout[i*Hq];
            float acc = 0.f;
            for (int k = lane; k < Hq; k += 32) acc += __ldcg(&h[k])*__ldg(&w[k]);
            acc = wred(acc);
            if (lane == 0)
                out[m*(Tq*Iq) + (Tq-1)*Iq + i] = sgm(acc + __ldg(&bout[i]));
        }
    }
}

extern "C" void kernel_launch(void* const* d_in, const int* in_sizes, int n_in,
                              void* d_out, int out_size)
{
    vae_kernel<<<NBLK, NTHR>>>(
        (const float*)d_in[0],  (const float*)d_in[1],
        (const float*)d_in[2],  (const float*)d_in[3],
        (const float*)d_in[4],  (const float*)d_in[5],
        (const float*)d_in[6],  (const float*)d_in[7],
        (const float*)d_in[8],  (const float*)d_in[9],
        (const float*)d_in[10], (const float*)d_in[11],
        (const float*)d_in[12], (const float*)d_in[13],
        (const float*)d_in[14], (const float*)d_in[15],
        (const float*)d_in[16], (const float*)d_in[17],
        (const float*)d_in[18], (const float*)d_in[19],
        (const float*)d_in[20], (const float*)d_in[21],
        (float*)d_out);
}